// round 7
// baseline (speedup 1.0000x reference)
#include <cuda_runtime.h>
#include <math.h>

#define DT 0.01f
#define SEG    32                      // actions per thread (k_final)
#define TPB    256
#define NTILE  1024                    // 8388608 / 8192
#define TILE   (TPB * SEG)             // 8192 floats per tile
#define SSTR   36                      // padded smem stride (floats) per segment
#define TPB1B  4                       // tiles per block in pass 1
#define GRID1  (NTILE / TPB1B)         // 256

// Per-tile affine tuples. (A,P,X,V): v' = A*v + V ; x' = x + P*v + X
__device__ float4 g_blk[NTILE];

__device__ __forceinline__ float4 comp(float4 f, float4 g) {
    float4 r;
    r.x = g.x * f.x;
    r.y = f.y + g.y * f.x;
    r.z = f.z + g.y * f.w + g.z;
    r.w = g.x * f.w + g.w;
    return r;
}
__device__ __forceinline__ float4 ident() { return make_float4(1.f, 0.f, 0.f, 0.f); }

__device__ __forceinline__ float4 shfl_up4(float4 v, int d, unsigned m) {
    float4 r;
    r.x = __shfl_up_sync(m, v.x, d);
    r.y = __shfl_up_sync(m, v.y, d);
    r.z = __shfl_up_sync(m, v.z, d);
    r.w = __shfl_up_sync(m, v.w, d);
    return r;
}

__device__ __forceinline__ void get_coeffs(const float* mass, const float* fric,
                                           float& alpha, float& beta) {
    float m_safe = fabsf(mass[0]) + 0.001f;
    beta  = DT / m_safe;
    alpha = 1.0f - fric[0] * beta;
}

// ---------------- Pass 1: per-tile tuples; 4 tiles/block, barrier-free loop ----------------
// Per tile (zero initial state):  v_z = beta*W,  W = sum_i alpha^(8191-i)*a_i
//                                 x_z = DT*(beta*S - alpha*beta*W)/(1-alpha),  S = sum_i a_i
__global__ void __launch_bounds__(TPB)
k_partial(const float* __restrict__ act,
          const float* __restrict__ mass,
          const float* __restrict__ fric) {
    __shared__ float2 wred[TPB1B][TPB / 32];
    int tid = threadIdx.x, lane = tid & 31, wid = tid >> 5;

    float alpha, beta;
    get_coeffs(mass, fric, alpha, beta);
    float l2a  = log2f(alpha);
    float w0   = exp2f(l2a * (float)(8191 - 4 * tid));  // weight of thread's first element
    float step = exp2f(l2a * -1024.0f);                 // advance 1024 elements
    float ai   = 1.0f / alpha;
    float ai2  = ai * ai;
    float ai3  = ai2 * ai;

    const float4* g4 = reinterpret_cast<const float4*>(act)
                     + (size_t)blockIdx.x * TPB1B * (TILE / 4);

    #pragma unroll
    for (int j = 0; j < TPB1B; j++) {
        const float4* t4 = g4 + j * (TILE / 4);
        float w = w0;
        float acc0 = 0.f, acc1 = 0.f, acc2 = 0.f, acc3 = 0.f;
        float s0 = 0.f, s1 = 0.f, s2 = 0.f, s3 = 0.f;
        #pragma unroll
        for (int r = 0; r < TILE / 4 / TPB; r++) {      // 8 independent loads
            float4 a = t4[r * TPB + tid];
            acc0 = fmaf(a.x, w, acc0);
            acc1 = fmaf(a.y, w, acc1);
            acc2 = fmaf(a.z, w, acc2);
            acc3 = fmaf(a.w, w, acc3);
            s0 += a.x; s1 += a.y; s2 += a.z; s3 += a.w;
            w *= step;
        }
        float W = fmaf(ai3, acc3, fmaf(ai2, acc2, fmaf(ai, acc1, acc0)));
        float S = (s0 + s1) + (s2 + s3);
        #pragma unroll
        for (int d = 16; d > 0; d >>= 1) {
            W += __shfl_down_sync(0xffffffffu, W, d);
            S += __shfl_down_sync(0xffffffffu, S, d);
        }
        if (lane == 0) wred[j][wid] = make_float2(S, W);
    }
    __syncthreads();

    // threads 0..31 finalize: 8-lane subgroup per tile (masks cover exactly the subgroup)
    if (tid < 32) {
        int j = tid >> 3, i = tid & 7;
        float2 p = wred[j][i];
        float S = p.x, W = p.y;
        #pragma unroll
        for (int d = 4; d > 0; d >>= 1) {
            S += __shfl_down_sync(0xffffffffu, S, d, 8);
            W += __shfl_down_sync(0xffffffffu, W, d, 8);
        }
        if (i == 0) {
            float A = alpha;
            #pragma unroll
            for (int k = 0; k < 13; k++) A *= A;        // alpha^8192
            float denom = 1.0f - alpha;
            if (fabsf(denom) < 1e-12f) denom = 1e-12f;
            float P  = DT * alpha * (1.0f - A) / denom;
            float vz = beta * W;
            float xz = DT * (beta * S - alpha * vz) / denom;
            g_blk[blockIdx.x * TPB1B + j] = make_float4(A, P, xz, vz);
        }
    }
}

// ---------------- Pass 2 (fused): per-block redundant scan + replay + fixup + store ----------------
__global__ void __launch_bounds__(TPB)
k_final(const float* __restrict__ act,
        const float* __restrict__ initst,
        const float* __restrict__ mass,
        const float* __restrict__ fric,
        float2* __restrict__ out2) {
    __shared__ __align__(16) float s[TPB * SSTR];       // tile; later aliased as output staging
    __shared__ float4 wtot[TPB / 32];
    __shared__ float4 sblk[TPB / 32];
    __shared__ float4 s_e;
    int tid = threadIdx.x, lane = tid & 31, wid = tid >> 5;
    int bid = blockIdx.x;
    int g   = bid * TPB + tid;

    // coalesced tile load -> padded smem (issue ASAP)
    {
        const float4* g4 = reinterpret_cast<const float4*>(act) + (size_t)bid * (TILE / 4);
        #pragma unroll
        for (int r = 0; r < TILE / 4 / TPB; r++) {
            int i4 = tid + TPB * r;
            float4 v = g4[i4];
            *reinterpret_cast<float4*>(&s[(i4 >> 3) * SSTR + (i4 & 7) * 4]) = v;
        }
    }

    // ---- redundant scan of the 1024 tile tuples; pick exclusive prefix for this bid ----
    {
        float4 t0 = g_blk[tid * 4 + 0];
        float4 t1 = g_blk[tid * 4 + 1];
        float4 t2 = g_blk[tid * 4 + 2];
        float4 t3 = g_blk[tid * 4 + 3];
        float4 acc = comp(comp(comp(t0, t1), t2), t3);
        #pragma unroll
        for (int d = 1; d < 32; d <<= 1) {
            float4 up = shfl_up4(acc, d, 0xffffffffu);
            if (lane >= d) acc = comp(up, acc);
        }
        if (lane == 31) sblk[wid] = acc;
        __syncthreads();
        if (tid < TPB / 32) {                            // lanes 0..7 of warp 0, mask 0xff
            float4 c = sblk[tid];
            #pragma unroll
            for (int d = 1; d < TPB / 32; d <<= 1) {
                float4 up = shfl_up4(c, d, 0xffu);
                if (tid >= d) c = comp(up, c);
            }
            sblk[tid] = c;
        }
        __syncthreads();
        float4 lexcl = shfl_up4(acc, 1, 0xffffffffu);
        if (lane == 0) lexcl = ident();
        float4 wexcl = (wid == 0) ? ident() : sblk[wid - 1];
        if (tid == (bid >> 2)) {
            float4 p = comp(wexcl, lexcl);               // exclusive prefix of tile 4*tid
            int rr = bid & 3;
            if (rr > 0) p = comp(p, t0);
            if (rr > 1) p = comp(p, t1);
            if (rr > 2) p = comp(p, t2);
            s_e = p;                                     // exclusive prefix of tile bid
        }
    }
    __syncthreads();   // tile STS + s_e both complete

    float alpha, beta;
    get_coeffs(mass, fric, alpha, beta);
    float A = alpha;
    #pragma unroll
    for (int j = 0; j < 5; j++) A *= A;                 // alpha^32
    float denom = 1.0f - alpha;
    float Pc = (denom != 0.f) ? (DT * alpha * (1.f - A) / denom) : (DT * (float)SEG);

    // zero-state replay in registers
    float2 r[SEG];
    const float* my = s + tid * SSTR;
    float v = 0.f, x = 0.f;
    #pragma unroll
    for (int j = 0; j < SEG / 4; j++) {
        float4 a = *reinterpret_cast<const float4*>(my + 4 * j);
        v = alpha * v + beta * a.x; x += DT * v; r[4 * j + 0] = make_float2(x, v);
        v = alpha * v + beta * a.y; x += DT * v; r[4 * j + 1] = make_float2(x, v);
        v = alpha * v + beta * a.z; x += DT * v; r[4 * j + 2] = make_float2(x, v);
        v = alpha * v + beta * a.w; x += DT * v; r[4 * j + 3] = make_float2(x, v);
    }

    // in-block ordered scan of thread tuples
    float4 val = make_float4(A, Pc, x, v);
    #pragma unroll
    for (int d = 1; d < 32; d <<= 1) {
        float4 up = shfl_up4(val, d, 0xffffffffu);
        if (lane >= d) val = comp(up, val);
    }
    if (lane == 31) wtot[wid] = val;
    __syncthreads();
    if (tid < TPB / 32) {
        float4 c = wtot[tid];
        #pragma unroll
        for (int d = 1; d < TPB / 32; d <<= 1) {
            float4 up = shfl_up4(c, d, 0xffu);
            if (tid >= d) c = comp(up, c);
        }
        wtot[tid] = c;
    }
    __syncthreads();
    float4 wexcl = (wid == 0) ? ident() : wtot[wid - 1];
    float4 lexcl = shfl_up4(val, 1, 0xffffffffu);
    if (lane == 0) lexcl = ident();
    float4 e = comp(s_e, comp(wexcl, lexcl));

    float x0 = initst[0];
    float v0 = initst[1];
    float vin = e.x * v0 + e.w;
    float xin = x0 + e.y * v0 + e.z;

    if (g == 0) out2[0] = make_float2(x0, v0);

    // affine fixup of zero-state trajectory
    float ap = 1.f, pp = 0.f;
    #pragma unroll
    for (int k = 0; k < SEG; k++) {
        ap *= alpha;
        pp += DT * ap;
        r[k].x = xin + pp * vin + r[k].x;
        r[k].y = ap * vin + r[k].y;
    }

    // staged coalesced output (staging aliases the input tile smem)
    float2* sout = reinterpret_cast<float2*>(s);
    float2* out_base = out2 + 1 + (size_t)bid * TILE;
    #pragma unroll
    for (int half = 0; half < 2; half++) {
        __syncthreads();
        if ((tid >> 7) == half) {
            int t = tid & 127;
            #pragma unroll
            for (int k = 0; k < SEG; k++) sout[t * (SEG + 1) + k] = r[k];
        }
        __syncthreads();
        float2* gdst = out_base + half * (TILE / 2);
        #pragma unroll
        for (int w = 0; w < (TILE / 2) / TPB; w++) {
            int i2 = tid + TPB * w;
            gdst[i2] = sout[(i2 >> 5) * (SEG + 1) + (i2 & 31)];
        }
    }
}

extern "C" void kernel_launch(void* const* d_in, const int* in_sizes, int n_in,
                              void* d_out, int out_size) {
    const float* init = (const float*)d_in[0];
    const float* act  = (const float*)d_in[1];
    const float* mass = (const float*)d_in[2];
    const float* fric = (const float*)d_in[3];
    float2* out2 = (float2*)d_out;

    k_partial<<<GRID1, TPB>>>(act, mass, fric);
    k_final<<<NTILE, TPB>>>(act, init, mass, fric, out2);
}

// round 8
// speedup vs baseline: 1.0073x; 1.0073x over previous
#include <cuda_runtime.h>
#include <math.h>

#define DT 0.01f
#define SEG     16                     // actions per thread in k_final
#define TPB     256
#define TILE_F  (TPB * SEG)            // 4096 floats per k_final tile
#define NTILE_F 2048                   // 8388608 / 4096
#define SSTR    20                     // smem stride (floats): 80B = odd multiple of 16B
#define CHUNK   1024                   // elements per warp in k_partial
#define NCHUNK  8192                   // 8388608 / 1024

// Tuples (A,P,X,V): v' = A*v + V ; x' = x + P*v + X
__device__ float4 g_chunk[NCHUNK];     // per-1024-element chunk tuples
__device__ float4 g_pref [NTILE_F];    // exclusive prefix per k_final tile

__device__ __forceinline__ float4 comp(float4 f, float4 g) {
    float4 r;
    r.x = g.x * f.x;
    r.y = f.y + g.y * f.x;
    r.z = f.z + g.y * f.w + g.z;
    r.w = g.x * f.w + g.w;
    return r;
}
__device__ __forceinline__ float4 ident() { return make_float4(1.f, 0.f, 0.f, 0.f); }

__device__ __forceinline__ float4 shfl_up4(float4 v, int d, unsigned m) {
    float4 r;
    r.x = __shfl_up_sync(m, v.x, d);
    r.y = __shfl_up_sync(m, v.y, d);
    r.z = __shfl_up_sync(m, v.z, d);
    r.w = __shfl_up_sync(m, v.w, d);
    return r;
}

__device__ __forceinline__ void get_coeffs(const float* mass, const float* fric,
                                           float& alpha, float& beta) {
    float m_safe = fabsf(mass[0]) + 0.001f;
    beta  = DT / m_safe;
    alpha = 1.0f - fric[0] * beta;
}

// ---------------- Pass 1: warp-autonomous chunk tuples (no block sync) ----------------
// Chunk (zero init): v_z = beta*W, W = sum_i alpha^(1023-i)*a_i
//                    x_z = DT*(beta*S - alpha*v_z*? ) -> DT/(1-alpha)*(beta*S - alpha*beta*W)
__global__ void __launch_bounds__(TPB)
k_partial(const float* __restrict__ act,
          const float* __restrict__ mass,
          const float* __restrict__ fric) {
    int tid = threadIdx.x, lane = tid & 31, wid = tid >> 5;
    int chunk = blockIdx.x * (TPB / 32) + wid;

    float alpha, beta;
    get_coeffs(mass, fric, alpha, beta);
    float l2a  = log2f(alpha);
    float w    = exp2f(l2a * (float)(CHUNK - 1 - 4 * lane)); // weight of lane's first element
    float step = exp2f(l2a * -128.0f);                       // +128 elements per iteration
    float ai   = 1.0f / alpha;
    float ai2  = ai * ai;
    float ai3  = ai2 * ai;

    const float4* g4 = reinterpret_cast<const float4*>(act) + (size_t)chunk * (CHUNK / 4);

    float acc0 = 0.f, acc1 = 0.f, acc2 = 0.f, acc3 = 0.f;
    float s0 = 0.f, s1 = 0.f, s2 = 0.f, s3 = 0.f;
    #pragma unroll
    for (int r = 0; r < CHUNK / 4 / 32; r++) {               // 8 independent loads
        float4 a = g4[r * 32 + lane];
        acc0 = fmaf(a.x, w, acc0);
        acc1 = fmaf(a.y, w, acc1);
        acc2 = fmaf(a.z, w, acc2);
        acc3 = fmaf(a.w, w, acc3);
        s0 += a.x; s1 += a.y; s2 += a.z; s3 += a.w;
        w *= step;
    }
    float W = fmaf(ai3, acc3, fmaf(ai2, acc2, fmaf(ai, acc1, acc0)));
    float S = (s0 + s1) + (s2 + s3);
    #pragma unroll
    for (int d = 16; d > 0; d >>= 1) {
        W += __shfl_down_sync(0xffffffffu, W, d);
        S += __shfl_down_sync(0xffffffffu, S, d);
    }
    if (lane == 0) {
        float A = alpha;
        #pragma unroll
        for (int k = 0; k < 10; k++) A *= A;                 // alpha^1024
        float denom = 1.0f - alpha;
        if (fabsf(denom) < 1e-12f) denom = 1e-12f;
        float P  = DT * alpha * (1.0f - A) / denom;
        float vz = beta * W;
        float xz = DT * (beta * S - alpha * vz) / denom;
        g_chunk[chunk] = make_float4(A, P, xz, vz);
    }
}

// ---------------- Pass 2: scan 8192 chunk tuples -> 2048 tile prefixes ----------------
__global__ void __launch_bounds__(1024)
k_blockscan() {
    __shared__ float4 wt[32];
    int tid = threadIdx.x, lane = tid & 31, wid = tid >> 5;

    float4 c0 = g_chunk[tid * 8 + 0];
    float4 c1 = g_chunk[tid * 8 + 1];
    float4 c2 = g_chunk[tid * 8 + 2];
    float4 c3 = g_chunk[tid * 8 + 3];
    float4 c4 = g_chunk[tid * 8 + 4];
    float4 c5 = g_chunk[tid * 8 + 5];
    float4 c6 = g_chunk[tid * 8 + 6];
    float4 c7 = g_chunk[tid * 8 + 7];
    float4 h0 = comp(comp(comp(c0, c1), c2), c3);            // first half (tile 2*tid)
    float4 val = comp(comp(comp(comp(h0, c4), c5), c6), c7); // full 8-chunk tuple

    #pragma unroll
    for (int d = 1; d < 32; d <<= 1) {
        float4 up = shfl_up4(val, d, 0xffffffffu);
        if (lane >= d) val = comp(up, val);
    }
    if (lane == 31) wt[wid] = val;
    __syncthreads();
    if (wid == 0) {
        float4 c = wt[lane];
        #pragma unroll
        for (int d = 1; d < 32; d <<= 1) {
            float4 up = shfl_up4(c, d, 0xffffffffu);
            if (lane >= d) c = comp(up, c);
        }
        wt[lane] = c;
    }
    __syncthreads();
    float4 wexcl = (wid == 0) ? ident() : wt[wid - 1];
    float4 lexcl = shfl_up4(val, 1, 0xffffffffu);
    if (lane == 0) lexcl = ident();
    float4 E = comp(wexcl, lexcl);                           // exclusive prefix @ chunk 8*tid

    g_pref[2 * tid]     = E;
    g_pref[2 * tid + 1] = comp(E, h0);
}

// ---------------- Pass 3: replay (SEG=16) + in-block scan + fixup + coalesced store ----------------
__global__ void __launch_bounds__(TPB)
k_final(const float* __restrict__ act,
        const float* __restrict__ initst,
        const float* __restrict__ mass,
        const float* __restrict__ fric,
        float2* __restrict__ out2) {
    __shared__ __align__(16) float s[TPB * SSTR];            // 20480B; aliased for output staging
    __shared__ float4 wtot[TPB / 32];
    int tid = threadIdx.x, lane = tid & 31, wid = tid >> 5;
    int bid = blockIdx.x;

    // coalesced tile load -> padded smem (segment-major)
    {
        const float4* g4 = reinterpret_cast<const float4*>(act) + (size_t)bid * (TILE_F / 4);
        #pragma unroll
        for (int r = 0; r < TILE_F / 4 / TPB; r++) {         // 4 iterations
            int i4 = tid + TPB * r;
            float4 v = g4[i4];
            *reinterpret_cast<float4*>(&s[(i4 >> 2) * SSTR + (i4 & 3) * 4]) = v;
        }
    }
    __syncthreads();

    float alpha, beta;
    get_coeffs(mass, fric, alpha, beta);
    float A = alpha;
    #pragma unroll
    for (int j = 0; j < 4; j++) A *= A;                      // alpha^16
    float denom = 1.0f - alpha;
    float Pc = (denom != 0.f) ? (DT * alpha * (1.f - A) / denom) : (DT * (float)SEG);

    // zero-state replay in registers
    float2 r[SEG];
    const float* my = s + tid * SSTR;
    float v = 0.f, x = 0.f;
    #pragma unroll
    for (int j = 0; j < SEG / 4; j++) {
        float4 a = *reinterpret_cast<const float4*>(my + 4 * j);
        v = alpha * v + beta * a.x; x += DT * v; r[4 * j + 0] = make_float2(x, v);
        v = alpha * v + beta * a.y; x += DT * v; r[4 * j + 1] = make_float2(x, v);
        v = alpha * v + beta * a.z; x += DT * v; r[4 * j + 2] = make_float2(x, v);
        v = alpha * v + beta * a.w; x += DT * v; r[4 * j + 3] = make_float2(x, v);
    }

    // in-block ordered scan of thread tuples
    float4 val = make_float4(A, Pc, x, v);
    #pragma unroll
    for (int d = 1; d < 32; d <<= 1) {
        float4 up = shfl_up4(val, d, 0xffffffffu);
        if (lane >= d) val = comp(up, val);
    }
    if (lane == 31) wtot[wid] = val;
    __syncthreads();
    if (tid < TPB / 32) {
        float4 c = wtot[tid];
        #pragma unroll
        for (int d = 1; d < TPB / 32; d <<= 1) {
            float4 up = shfl_up4(c, d, 0xffu);
            if (tid >= d) c = comp(up, c);
        }
        wtot[tid] = c;
    }
    __syncthreads();
    float4 wexcl = (wid == 0) ? ident() : wtot[wid - 1];
    float4 lexcl = shfl_up4(val, 1, 0xffffffffu);
    if (lane == 0) lexcl = ident();
    float4 e = comp(g_pref[bid], comp(wexcl, lexcl));

    float x0 = initst[0];
    float v0 = initst[1];
    float vin = e.x * v0 + e.w;
    float xin = x0 + e.y * v0 + e.z;

    if (bid == 0 && tid == 0) out2[0] = make_float2(x0, v0);

    // affine fixup
    float ap = 1.f, pp = 0.f;
    #pragma unroll
    for (int k = 0; k < SEG; k++) {
        ap *= alpha;
        pp += DT * ap;
        r[k].x = xin + pp * vin + r[k].x;
        r[k].y = ap * vin + r[k].y;
    }

    // staged coalesced output (staging aliases the input tile smem: 128*17*8 = 17408B <= 20480B)
    float2* sout = reinterpret_cast<float2*>(s);
    float2* out_base = out2 + 1 + (size_t)bid * TILE_F;
    #pragma unroll
    for (int half = 0; half < 2; half++) {
        __syncthreads();
        if ((tid >> 7) == half) {
            int t = tid & 127;
            #pragma unroll
            for (int k = 0; k < SEG; k++) sout[t * (SEG + 1) + k] = r[k];
        }
        __syncthreads();
        float2* gdst = out_base + half * (TILE_F / 2);
        #pragma unroll
        for (int w = 0; w < (TILE_F / 2) / TPB; w++) {       // 8 iterations
            int i2 = tid + TPB * w;
            gdst[i2] = sout[(i2 >> 4) * (SEG + 1) + (i2 & 15)];
        }
    }
}

extern "C" void kernel_launch(void* const* d_in, const int* in_sizes, int n_in,
                              void* d_out, int out_size) {
    const float* init = (const float*)d_in[0];
    const float* act  = (const float*)d_in[1];
    const float* mass = (const float*)d_in[2];
    const float* fric = (const float*)d_in[3];
    float2* out2 = (float2*)d_out;

    k_partial<<<NCHUNK / (TPB / 32), TPB>>>(act, mass, fric);   // 1024 blocks
    k_blockscan<<<1, 1024>>>();
    k_final<<<NTILE_F, TPB>>>(act, init, mass, fric, out2);
}

// round 9
// speedup vs baseline: 1.2065x; 1.1978x over previous
#include <cuda_runtime.h>
#include <math.h>

#define DT 0.01f
#define SEG    32                      // actions per thread (k_final)
#define TPB    256
#define NTILE  1024                    // 8388608 / 8192
#define TILE   (TPB * SEG)             // 8192 floats per tile
#define SSTR   36                      // padded smem stride (floats) per segment

// Per-tile affine tuples. (A,P,X,V): v' = A*v + V ; x' = x + P*v + X
__device__ float4 g_blk[NTILE];

__device__ __forceinline__ float4 comp(float4 f, float4 g) {
    float4 r;
    r.x = g.x * f.x;
    r.y = f.y + g.y * f.x;
    r.z = f.z + g.y * f.w + g.z;
    r.w = g.x * f.w + g.w;
    return r;
}
__device__ __forceinline__ float4 ident() { return make_float4(1.f, 0.f, 0.f, 0.f); }

__device__ __forceinline__ float4 shfl_up4(float4 v, int d, unsigned m) {
    float4 r;
    r.x = __shfl_up_sync(m, v.x, d);
    r.y = __shfl_up_sync(m, v.y, d);
    r.z = __shfl_up_sync(m, v.z, d);
    r.w = __shfl_up_sync(m, v.w, d);
    return r;
}

__device__ __forceinline__ void get_coeffs(const float* mass, const float* fric,
                                           float& alpha, float& beta, float& fb) {
    float m_safe = fabsf(mass[0]) + 0.001f;
    beta  = DT / m_safe;
    fb    = fric[0] * beta;            // = 1 - alpha, computed without cancellation
    alpha = 1.0f - fb;
}

// ---------------- Pass 1: per-tile tuple via two parallel reductions (R5, proven) ----------------
__global__ void __launch_bounds__(TPB)
k_partial(const float* __restrict__ act,
          const float* __restrict__ mass,
          const float* __restrict__ fric) {
    __shared__ float2 wred[TPB / 32];
    int tid = threadIdx.x, lane = tid & 31, wid = tid >> 5;

    float alpha, beta, fb;
    get_coeffs(mass, fric, alpha, beta, fb);
    float l2a  = log2f(alpha);
    float w    = exp2f(l2a * (float)(8191 - 4 * tid));
    float step = exp2f(l2a * -1024.0f);

    const float4* g4 = reinterpret_cast<const float4*>(act) + (size_t)blockIdx.x * (TILE / 4);

    float acc0 = 0.f, acc1 = 0.f, acc2 = 0.f, acc3 = 0.f;
    float s0 = 0.f, s1 = 0.f, s2 = 0.f, s3 = 0.f;
    #pragma unroll
    for (int r = 0; r < TILE / 4 / TPB; r++) {
        float4 a = g4[r * TPB + tid];
        acc0 = fmaf(a.x, w, acc0);
        acc1 = fmaf(a.y, w, acc1);
        acc2 = fmaf(a.z, w, acc2);
        acc3 = fmaf(a.w, w, acc3);
        s0 += a.x; s1 += a.y; s2 += a.z; s3 += a.w;
        w *= step;
    }
    float ai  = 1.0f / alpha;
    float ai2 = ai * ai;
    float W = fmaf(ai2 * ai, acc3, fmaf(ai2, acc2, fmaf(ai, acc1, acc0)));
    float S = (s0 + s1) + (s2 + s3);

    #pragma unroll
    for (int d = 16; d > 0; d >>= 1) {
        W += __shfl_down_sync(0xffffffffu, W, d);
        S += __shfl_down_sync(0xffffffffu, S, d);
    }
    if (lane == 0) wred[wid] = make_float2(S, W);
    __syncthreads();
    if (tid == 0) {
        float St = 0.f, Wt = 0.f;
        #pragma unroll
        for (int i = 0; i < TPB / 32; i++) { St += wred[i].x; Wt += wred[i].y; }

        float A = alpha;
        #pragma unroll
        for (int j = 0; j < 13; j++) A *= A;            // alpha^8192
        float denom = fb;
        if (fabsf(denom) < 1e-12f) denom = 1e-12f;
        float P  = DT * alpha * (1.0f - A) / denom;
        float vz = beta * Wt;
        float xz = DT * (beta * St - alpha * vz) / denom;
        g_blk[blockIdx.x] = make_float4(A, P, xz, vz);
    }
}

// ---------------- Pass 2: exclusive scan of 1024 tile tuples (R5, proven) ----------------
__global__ void __launch_bounds__(1024)
k_blockscan() {
    __shared__ float4 wt[32];
    int tid = threadIdx.x, lane = tid & 31, wid = tid >> 5;

    float4 val = g_blk[tid];
    #pragma unroll
    for (int d = 1; d < 32; d <<= 1) {
        float4 up = shfl_up4(val, d, 0xffffffffu);
        if (lane >= d) val = comp(up, val);
    }
    if (lane == 31) wt[wid] = val;
    __syncthreads();
    if (wid == 0) {
        float4 c = wt[lane];
        #pragma unroll
        for (int d = 1; d < 32; d <<= 1) {
            float4 up = shfl_up4(c, d, 0xffffffffu);
            if (lane >= d) c = comp(up, c);
        }
        wt[lane] = c;
    }
    __syncthreads();
    float4 wexcl = (wid == 0) ? ident() : wt[wid - 1];
    float4 lexcl = shfl_up4(val, 1, 0xffffffffu);
    if (lane == 0) lexcl = ident();
    g_blk[tid] = comp(wexcl, lexcl);
}

// ---------------- Pass 3: closed-form tuples + scan + quarter-round replay/store ----------------
__global__ void __launch_bounds__(TPB)
k_final(const float* __restrict__ act,
        const float* __restrict__ initst,
        const float* __restrict__ mass,
        const float* __restrict__ fric,
        float2* __restrict__ out2) {
    __shared__ __align__(16) float s[TPB * SSTR];       // 36864B input tile (transposed)
    __shared__ __align__(16) float2 sout[64 * (SEG + 1)];  // 16896B quarter staging
    __shared__ float4 wtot[TPB / 32];
    int tid = threadIdx.x, lane = tid & 31, wid = tid >> 5;
    int bid = blockIdx.x;

    // coalesced tile load -> padded smem (segment-major)
    {
        const float4* g4 = reinterpret_cast<const float4*>(act) + (size_t)bid * (TILE / 4);
        #pragma unroll
        for (int r = 0; r < TILE / 4 / TPB; r++) {
            int i4 = tid + TPB * r;
            float4 v = g4[i4];
            *reinterpret_cast<float4*>(&s[(i4 >> 3) * SSTR + (i4 & 7) * 4]) = v;
        }
    }
    __syncthreads();

    float alpha, beta, fb;
    get_coeffs(mass, fric, alpha, beta, fb);
    float a2  = alpha * alpha;
    float a4  = a2 * a2;
    float a8  = a4 * a4;
    float a16 = a8 * a8;
    float A   = a16 * a16;                               // alpha^32
    float a31 = a16 * a8 * a4 * a2 * alpha;              // alpha^31
    float denom = fb;
    if (fabsf(denom) < 1e-12f) denom = 1e-12f;
    float Pc = DT * alpha * (1.0f - A) / denom;
    float ai  = 1.0f / alpha;
    float ai2 = ai * ai;
    float ai4 = ai2 * ai2;

    // per-thread segment tuple via closed-form dot products (no serial chain)
    const float* my = s + tid * SSTR;
    float acc0 = 0.f, acc1 = 0.f, acc2 = 0.f, acc3 = 0.f;
    float s0 = 0.f, s1 = 0.f, s2 = 0.f, s3 = 0.f;
    float w = a31;
    #pragma unroll
    for (int j = 0; j < SEG / 4; j++) {
        float4 a = *reinterpret_cast<const float4*>(my + 4 * j);
        acc0 = fmaf(a.x, w, acc0);
        acc1 = fmaf(a.y, w, acc1);
        acc2 = fmaf(a.z, w, acc2);
        acc3 = fmaf(a.w, w, acc3);
        s0 += a.x; s1 += a.y; s2 += a.z; s3 += a.w;
        w *= ai4;
    }
    float W = fmaf(ai2 * ai, acc3, fmaf(ai2, acc2, fmaf(ai, acc1, acc0)));
    float S = (s0 + s1) + (s2 + s3);
    float vz = beta * W;
    float xz = DT * (beta * S - alpha * vz) / denom;

    // in-block ordered scan of thread tuples
    float4 val = make_float4(A, Pc, xz, vz);
    #pragma unroll
    for (int d = 1; d < 32; d <<= 1) {
        float4 up = shfl_up4(val, d, 0xffffffffu);
        if (lane >= d) val = comp(up, val);
    }
    if (lane == 31) wtot[wid] = val;
    __syncthreads();
    if (tid < TPB / 32) {
        float4 c = wtot[tid];
        #pragma unroll
        for (int d = 1; d < TPB / 32; d <<= 1) {
            float4 up = shfl_up4(c, d, 0xffu);
            if (tid >= d) c = comp(up, c);
        }
        wtot[tid] = c;
    }
    __syncthreads();
    float4 wexcl = (wid == 0) ? ident() : wtot[wid - 1];
    float4 lexcl = shfl_up4(val, 1, 0xffffffffu);
    if (lane == 0) lexcl = ident();
    float4 e = comp(g_blk[bid], comp(wexcl, lexcl));

    float x0 = initst[0];
    float v0 = initst[1];
    float vin = e.x * v0 + e.w;
    float xin = x0 + e.y * v0 + e.z;

    if (bid == 0 && tid == 0) out2[0] = make_float2(x0, v0);

    // quarter rounds: 64 threads replay from true state into staging; all store coalesced
    float2* out_base = out2 + 1 + (size_t)bid * TILE;
    #pragma unroll
    for (int q = 0; q < 4; q++) {
        if ((tid >> 6) == q) {
            int t = tid & 63;
            float vv = vin, xx = xin;
            float2* so = sout + t * (SEG + 1);
            #pragma unroll
            for (int j = 0; j < SEG / 4; j++) {
                float4 a = *reinterpret_cast<const float4*>(my + 4 * j);
                vv = alpha * vv + beta * a.x; xx += DT * vv; so[4 * j + 0] = make_float2(xx, vv);
                vv = alpha * vv + beta * a.y; xx += DT * vv; so[4 * j + 1] = make_float2(xx, vv);
                vv = alpha * vv + beta * a.z; xx += DT * vv; so[4 * j + 2] = make_float2(xx, vv);
                vv = alpha * vv + beta * a.w; xx += DT * vv; so[4 * j + 3] = make_float2(xx, vv);
            }
        }
        __syncthreads();
        float2* gdst = out_base + q * (64 * SEG);
        #pragma unroll
        for (int w2 = 0; w2 < (64 * SEG) / TPB; w2++) {     // 8 iterations
            int i2 = tid + TPB * w2;
            gdst[i2] = sout[(i2 >> 5) * (SEG + 1) + (i2 & 31)];
        }
        __syncthreads();
    }
}

extern "C" void kernel_launch(void* const* d_in, const int* in_sizes, int n_in,
                              void* d_out, int out_size) {
    const float* init = (const float*)d_in[0];
    const float* act  = (const float*)d_in[1];
    const float* mass = (const float*)d_in[2];
    const float* fric = (const float*)d_in[3];
    float2* out2 = (float2*)d_out;

    k_partial<<<NTILE, TPB>>>(act, mass, fric);
    k_blockscan<<<1, 1024>>>();
    k_final<<<NTILE, TPB>>>(act, init, mass, fric, out2);
}